// round 11
// baseline (speedup 1.0000x reference)
#include <cuda_runtime.h>
#include <cuda_fp16.h>
#include <math.h>

#define D      1024
#define PD     32
#define NPAT   256
#define TOPK   4
#define THREADS 256

#define TBL_N  (NPAT * D * PD)   // 8,388,608 elements per table
#define N4     (TBL_N / 4)       // 2,097,152 float4 per table
#define CVT_CTAS 2048
#define CVT_STRIDE (CVT_CTAS * 256)   // 524288; N4 / CVT_STRIDE = 4

// fp16 copies of the weight tables (allocation-free __device__ scratch)
struct alignas(16) H8 { __half2 a, b, c, d; };
struct alignas(8)  H4 { __half2 a, b; };

__device__ H8 g_vd_h[TBL_N / 8];   // [NPAT][D][PD] as half, 16 MB
__device__ H8 g_vu_h[TBL_N / 8];   // [NPAT][PD][D] as half, 16 MB

// ---------------- prologue: fp32 -> fp16 for BOTH tables, one launch ----------
// 2048 CTAs x 256 thr; each thread converts 8 float4s (4 vd + 4 vu) with all
// 8 loads issued back-to-back (MLP=8) before any dependent convert/store.
__global__ __launch_bounds__(256) void convert_kernel(
    const float4* __restrict__ vd, const float4* __restrict__ vu,
    uint2* __restrict__ dvd, uint2* __restrict__ dvu)
{
    const int base = blockIdx.x * 256 + threadIdx.x;

    float4 a[4], b[4];
    #pragma unroll
    for (int i = 0; i < 4; i++) a[i] = __ldcs(&vd[base + i * CVT_STRIDE]);
    #pragma unroll
    for (int i = 0; i < 4; i++) b[i] = __ldcs(&vu[base + i * CVT_STRIDE]);

    #pragma unroll
    for (int i = 0; i < 4; i++) {
        __half2 h0 = __floats2half2_rn(a[i].x, a[i].y);
        __half2 h1 = __floats2half2_rn(a[i].z, a[i].w);
        uint2 o;
        o.x = *reinterpret_cast<unsigned int*>(&h0);
        o.y = *reinterpret_cast<unsigned int*>(&h1);
        dvd[base + i * CVT_STRIDE] = o;
    }
    #pragma unroll
    for (int i = 0; i < 4; i++) {
        __half2 h0 = __floats2half2_rn(b[i].x, b[i].y);
        __half2 h1 = __floats2half2_rn(b[i].z, b[i].w);
        uint2 o;
        o.x = *reinterpret_cast<unsigned int*>(&h0);
        o.y = *reinterpret_cast<unsigned int*>(&h1);
        dvu[base + i * CVT_STRIDE] = o;
    }
}

// ---------------- fused per-token kernel (unchanged from R10) ----------------
__global__ __launch_bounds__(THREADS) void peer_fused_kernel(
    const float* __restrict__ x,
    const float* __restrict__ hw,      // [PD, D] fp32 (routing stays exact)
    const float* __restrict__ keys,    // [NPAT, PD]
    const float* __restrict__ scale,   // [1]
    float* __restrict__ out)
{
    __shared__ float xs[D];
    __shared__ float hs[PD];
    __shared__ float sims[NPAT];
    __shared__ float partial[8 * 32];   // [warp][j]
    __shared__ float proj[PD];
    __shared__ float wk_s[TOPK];
    __shared__ int   idx_s[TOPK];
    __shared__ float kval_s[TOPK];
    __shared__ float scale_s;

    const int tok  = blockIdx.x;
    const int tid  = threadIdx.x;
    const int lane = tid & 31;
    const int w    = tid >> 5;

    // ---- stage x (coalesced float4) ----
    const float4* xg4 = reinterpret_cast<const float4*>(x + (size_t)tok * D);
    float4 xv4 = xg4[tid];
    reinterpret_cast<float4*>(xs)[tid] = xv4;
    if (tid == 0) scale_s = scale[0];
    __syncthreads();

    // ---- hash: h[j] = dot(hw[j], x); warp w owns j = 4w..4w+3 ----
    {
        const float4* hw4 = reinterpret_cast<const float4*>(hw);
        const float4* xs4 = reinterpret_cast<const float4*>(xs);
        #pragma unroll
        for (int jj = 0; jj < 4; jj++) {
            const int j = w * 4 + jj;
            float acc = 0.f;
            #pragma unroll
            for (int i = 0; i < 8; i++) {
                float4 a = hw4[j * (D / 4) + lane + 32 * i];
                float4 b = xs4[lane + 32 * i];
                acc += a.x * b.x + a.y * b.y + a.z * b.z + a.w * b.w;
            }
            #pragma unroll
            for (int off = 16; off; off >>= 1)
                acc += __shfl_xor_sync(0xFFFFFFFFu, acc, off);
            if (lane == 0) hs[j] = acc;
        }
    }
    __syncthreads();

    // ---- sim[n] = dot(keys[n], h): one pattern per thread ----
    {
        const float4* k4 = reinterpret_cast<const float4*>(keys + tid * PD);
        const float4* h4 = reinterpret_cast<const float4*>(hs);
        float s = 0.f;
        #pragma unroll
        for (int i = 0; i < 8; i++) {
            float4 a = k4[i]; float4 b = h4[i];
            s += a.x * b.x + a.y * b.y + a.z * b.z + a.w * b.w;
        }
        sims[tid] = s;
    }
    __syncthreads();

    // ---- top-4 (warp 0), ties -> lower index ----
    if (w == 0) {
        for (int k = 0; k < TOPK; k++) {
            float bv = -1e30f; int bi = 0;
            #pragma unroll
            for (int t = 0; t < 8; t++) {
                const int n = lane * 8 + t;
                const float v = sims[n];
                if (v > bv) { bv = v; bi = n; }
            }
            #pragma unroll
            for (int off = 16; off; off >>= 1) {
                const float ov = __shfl_xor_sync(0xFFFFFFFFu, bv, off);
                const int   oi = __shfl_xor_sync(0xFFFFFFFFu, bi, off);
                if (ov > bv || (ov == bv && oi < bi)) { bv = ov; bi = oi; }
            }
            if (lane == 0) { idx_s[k] = bi; kval_s[k] = bv; sims[bi] = -1e30f; }
            __syncwarp();
        }
        if (lane == 0) {
            const float m = kval_s[0];
            float e[TOPK]; float ssum = 0.f;
            #pragma unroll
            for (int k = 0; k < TOPK; k++) { e[k] = expf(kval_s[k] - m); ssum += e[k]; }
            const float sc = scale_s / ssum;
            #pragma unroll
            for (int k = 0; k < TOPK; k++) wk_s[k] = e[k] * sc;
        }
    }
    __syncthreads();

    // ---- expert loop on fp16 tables ----
    const int c    = lane & 3;
    const int dsub = lane >> 2;

    float2 o0 = make_float2(0.f, 0.f), o1 = make_float2(0.f, 0.f);

    for (int k = 0; k < TOPK; k++) {
        const int p = idx_s[k];
        const H8* vd8 = g_vd_h + (size_t)p * (D * PD / 8);

        float2 a0 = make_float2(0.f, 0.f), a1 = a0, a2 = a0, a3 = a0;
        const int dbase = w * 128 + dsub;
        #pragma unroll
        for (int i = 0; i < 16; i++) {
            const int d = dbase + i * 8;
            const float xv = xs[d];
            const H8 r = vd8[d * 4 + c];
            const float2 f0 = __half22float2(r.a);
            const float2 f1 = __half22float2(r.b);
            const float2 f2 = __half22float2(r.c);
            const float2 f3 = __half22float2(r.d);
            a0.x += xv * f0.x; a0.y += xv * f0.y;
            a1.x += xv * f1.x; a1.y += xv * f1.y;
            a2.x += xv * f2.x; a2.y += xv * f2.y;
            a3.x += xv * f3.x; a3.y += xv * f3.y;
        }
        #pragma unroll
        for (int off = 4; off < 32; off <<= 1) {
            a0.x += __shfl_xor_sync(0xFFFFFFFFu, a0.x, off);
            a0.y += __shfl_xor_sync(0xFFFFFFFFu, a0.y, off);
            a1.x += __shfl_xor_sync(0xFFFFFFFFu, a1.x, off);
            a1.y += __shfl_xor_sync(0xFFFFFFFFu, a1.y, off);
            a2.x += __shfl_xor_sync(0xFFFFFFFFu, a2.x, off);
            a2.y += __shfl_xor_sync(0xFFFFFFFFu, a2.y, off);
            a3.x += __shfl_xor_sync(0xFFFFFFFFu, a3.x, off);
            a3.y += __shfl_xor_sync(0xFFFFFFFFu, a3.y, off);
        }
        if (dsub == 0) {
            float* pw = partial + w * 32 + c * 8;
            pw[0] = a0.x; pw[1] = a0.y; pw[2] = a1.x; pw[3] = a1.y;
            pw[4] = a2.x; pw[5] = a2.y; pw[6] = a3.x; pw[7] = a3.y;
        }
        __syncthreads();

        if (tid < PD) {
            float s = 0.f;
            #pragma unroll
            for (int ww = 0; ww < 8; ww++) s += partial[ww * 32 + tid];
            const float sig = 1.f / (1.f + expf(-s));
            proj[tid] = s * sig * wk_s[k];       // silu(s) * w_k * scale
        }
        __syncthreads();

        const H4* vu4 = reinterpret_cast<const H4*>(g_vu_h) + (size_t)p * (PD * D / 4);
        #pragma unroll 8
        for (int j = 0; j < PD; j++) {
            const float pj = proj[j];            // smem broadcast
            const H4 r = vu4[j * (D / 4) + tid];
            const float2 f0 = __half22float2(r.a);
            const float2 f1 = __half22float2(r.b);
            o0.x += pj * f0.x; o0.y += pj * f0.y;
            o1.x += pj * f1.x; o1.y += pj * f1.y;
        }
    }

    float4 res;
    res.x = xv4.x + o0.x; res.y = xv4.y + o0.y;
    res.z = xv4.z + o1.x; res.w = xv4.w + o1.y;
    reinterpret_cast<float4*>(out)[(size_t)tok * (D / 4) + tid] = res;
}

// ---------------- launcher ----------------
extern "C" void kernel_launch(void* const* d_in, const int* in_sizes, int n_in,
                              void* d_out, int out_size) {
    const float* x     = (const float*)d_in[0];
    const float* hw    = (const float*)d_in[1];
    const float* keys  = (const float*)d_in[2];
    const float* vd    = (const float*)d_in[3];
    const float* vu    = (const float*)d_in[4];
    const float* scale = (const float*)d_in[5];
    float* out = (float*)d_out;

    const int ntok = in_sizes[0] / D;   // 2048

    convert_kernel<<<CVT_CTAS, 256>>>((const float4*)vd, (const float4*)vu,
                                      (uint2*)g_vd_h, (uint2*)g_vu_h);
    peer_fused_kernel<<<ntok, THREADS>>>(x, hw, keys, scale, out);
}

// round 13
// speedup vs baseline: 2.3069x; 2.3069x over previous
#include <cuda_runtime.h>
#include <math.h>

#define D      1024
#define PD     32
#define NPAT   256
#define TOPK   4
#define THREADS 256

__global__ __launch_bounds__(THREADS, 5) void peer_fused_kernel(
    const float* __restrict__ x,
    const float* __restrict__ hw,      // [PD, D]
    const float* __restrict__ keys,    // [NPAT, PD]
    const float* __restrict__ vd,      // [NPAT, D, PD]
    const float* __restrict__ vu,      // [NPAT, PD, D]
    const float* __restrict__ scale,   // [1]
    float* __restrict__ out)
{
    __shared__ float xs[D];
    __shared__ float hs[PD];
    __shared__ float sims[NPAT];
    __shared__ float partial[8 * 32];   // [warp][j]
    __shared__ float proj[PD];
    __shared__ float wk_s[TOPK];
    __shared__ int   idx_s[TOPK];
    __shared__ float kval_s[TOPK];
    __shared__ float scale_s;

    const int tok  = blockIdx.x;
    const int tid  = threadIdx.x;
    const int lane = tid & 31;
    const int w    = tid >> 5;

    // ---- stage x into smem (coalesced float4) ----
    const float4* xg4 = reinterpret_cast<const float4*>(x + (size_t)tok * D);
    float4 xv4 = xg4[tid];
    reinterpret_cast<float4*>(xs)[tid] = xv4;
    if (tid == 0) scale_s = scale[0];
    __syncthreads();

    // ---- hash: h[j] = dot(hw[j], x). warp w owns j = 4w..4w+3 ----
    {
        const float4* hw4 = reinterpret_cast<const float4*>(hw);
        const float4* xs4 = reinterpret_cast<const float4*>(xs);
        #pragma unroll
        for (int jj = 0; jj < 4; jj++) {
            const int j = w * 4 + jj;
            float acc = 0.f;
            #pragma unroll
            for (int i = 0; i < 8; i++) {
                float4 a = hw4[j * (D / 4) + lane + 32 * i];
                float4 b = xs4[lane + 32 * i];
                acc += a.x * b.x + a.y * b.y + a.z * b.z + a.w * b.w;
            }
            #pragma unroll
            for (int off = 16; off; off >>= 1)
                acc += __shfl_xor_sync(0xFFFFFFFFu, acc, off);
            if (lane == 0) hs[j] = acc;
        }
    }
    __syncthreads();

    // ---- sim[n] = dot(keys[n], h): one pattern per thread ----
    {
        const float4* k4 = reinterpret_cast<const float4*>(keys + tid * PD);
        const float4* h4 = reinterpret_cast<const float4*>(hs);
        float s = 0.f;
        #pragma unroll
        for (int i = 0; i < 8; i++) {
            float4 a = k4[i]; float4 b = h4[i];
            s += a.x * b.x + a.y * b.y + a.z * b.z + a.w * b.w;
        }
        sims[tid] = s;
    }
    __syncthreads();

    // ---- top-4 (warp 0), ties -> lower index (matches lax.top_k) ----
    if (w == 0) {
        for (int k = 0; k < TOPK; k++) {
            float bv = -1e30f; int bi = 0;
            #pragma unroll
            for (int t = 0; t < 8; t++) {
                const int n = lane * 8 + t;
                const float v = sims[n];
                if (v > bv) { bv = v; bi = n; }
            }
            #pragma unroll
            for (int off = 16; off; off >>= 1) {
                const float ov = __shfl_xor_sync(0xFFFFFFFFu, bv, off);
                const int   oi = __shfl_xor_sync(0xFFFFFFFFu, bi, off);
                if (ov > bv || (ov == bv && oi < bi)) { bv = ov; bi = oi; }
            }
            if (lane == 0) { idx_s[k] = bi; kval_s[k] = bv; sims[bi] = -1e30f; }
            __syncwarp();
        }
        if (lane == 0) {
            const float m = kval_s[0];           // pass 0 found the max
            float e[TOPK]; float ssum = 0.f;
            #pragma unroll
            for (int k = 0; k < TOPK; k++) { e[k] = expf(kval_s[k] - m); ssum += e[k]; }
            const float sc = scale_s / ssum;     // fold scale into the softmax weight
            #pragma unroll
            for (int k = 0; k < TOPK; k++) wk_s[k] = e[k] * sc;
        }
    }
    __syncthreads();

    // ---- expert loop: down-proj -> silu -> up-proj, w_k*scale folded into proj
    float4 oacc = make_float4(0.f, 0.f, 0.f, 0.f);
    const int jq   = lane & 7;   // j-quad (4 consecutive j per float4)
    const int dsub = lane >> 3;  // 4 d-subgroups per warp

    for (int k = 0; k < TOPK; k++) {
        const int p = idx_s[k];
        const float4* vd4 = reinterpret_cast<const float4*>(vd + (size_t)p * D * PD);

        // down: proj[j] = sum_d x[d] * vd[d][j]; warp reads 4 full 128B rows per request
        float4 acc = make_float4(0.f, 0.f, 0.f, 0.f);
        const int dbase = w * 128 + dsub * 32;
        #pragma unroll
        for (int i = 0; i < 32; i++) {
            const int d = dbase + i;
            const float xv = xs[d];
            const float4 r = vd4[d * (PD / 4) + jq];
            acc.x += xv * r.x; acc.y += xv * r.y;
            acc.z += xv * r.z; acc.w += xv * r.w;
        }
        // reduce over dsub within the warp (xor 8, 16)
        #pragma unroll
        for (int off = 8; off < 32; off <<= 1) {
            acc.x += __shfl_xor_sync(0xFFFFFFFFu, acc.x, off);
            acc.y += __shfl_xor_sync(0xFFFFFFFFu, acc.y, off);
            acc.z += __shfl_xor_sync(0xFFFFFFFFu, acc.z, off);
            acc.w += __shfl_xor_sync(0xFFFFFFFFu, acc.w, off);
        }
        if (dsub == 0)
            reinterpret_cast<float4*>(partial)[w * 8 + jq] = acc;
        __syncthreads();

        if (tid < PD) {
            float s = 0.f;
            #pragma unroll
            for (int ww = 0; ww < 8; ww++) s += partial[ww * 32 + tid];
            const float sig = 1.f / (1.f + expf(-s));
            proj[tid] = s * sig * wk_s[k];       // silu(s) * w_k * scale
        }
        __syncthreads();

        // up: oacc[d] += proj[j] * vu[j][d]; proj read as float4 (LDS.128 broadcast)
        const float4* vu4 = reinterpret_cast<const float4*>(vu + (size_t)p * PD * D);
        const float4* pj4 = reinterpret_cast<const float4*>(proj);
        #pragma unroll
        for (int jg = 0; jg < PD / 4; jg++) {
            const float4 pj = pj4[jg];
            const float4 r0 = vu4[(4 * jg + 0) * (D / 4) + tid];
            const float4 r1 = vu4[(4 * jg + 1) * (D / 4) + tid];
            const float4 r2 = vu4[(4 * jg + 2) * (D / 4) + tid];
            const float4 r3 = vu4[(4 * jg + 3) * (D / 4) + tid];
            oacc.x += pj.x * r0.x + pj.y * r1.x + pj.z * r2.x + pj.w * r3.x;
            oacc.y += pj.x * r0.y + pj.y * r1.y + pj.z * r2.y + pj.w * r3.y;
            oacc.z += pj.x * r0.z + pj.y * r1.z + pj.z * r2.z + pj.w * r3.z;
            oacc.w += pj.x * r0.w + pj.y * r1.w + pj.z * r2.w + pj.w * r3.w;
        }
        // no trailing sync needed: next iter's proj write is gated by the
        // post-partial __syncthreads (no thread reaches it before finishing
        // its up-phase reads of proj).
    }

    float4 res;
    res.x = xv4.x + oacc.x; res.y = xv4.y + oacc.y;
    res.z = xv4.z + oacc.z; res.w = xv4.w + oacc.w;
    reinterpret_cast<float4*>(out)[(size_t)tok * (D / 4) + tid] = res;
}

extern "C" void kernel_launch(void* const* d_in, const int* in_sizes, int n_in,
                              void* d_out, int out_size) {
    const float* x     = (const float*)d_in[0];
    const float* hw    = (const float*)d_in[1];
    const float* keys  = (const float*)d_in[2];
    const float* vd    = (const float*)d_in[3];
    const float* vu    = (const float*)d_in[4];
    const float* scale = (const float*)d_in[5];
    float* out = (float*)d_out;

    const int ntok = in_sizes[0] / D;   // B*T = 2048
    peer_fused_kernel<<<ntok, THREADS>>>(x, hw, keys, vd, vu, scale, out);
}